// round 1
// baseline (speedup 1.0000x reference)
#include <cuda_runtime.h>
#include <math.h>

// ----------------------------------------------------------------------------
// Problem constants (MultiSizeProjHead):
//   x:        (256, 128, 1024) f32
//   psizes:   (256,) int32 in {8,16,32,64}
//   W_in:     (4096, 1024), b_in: (4096,)
//   W_shared: (672, 4096),  b_shared: (672,)
//   W_res:    (672, 1024),  b_res: (672,)
//   out:      (256, 128, max_ps*21) f32
// ----------------------------------------------------------------------------
#define EMBED   1024
#define INTER   4096
#define SBASE   672
#define OUTD    21
#define NSAMP   256
#define PTOK    128
#define MROWS   (NSAMP * PTOK)
#define TTOT    2520   // 168 + 336 + 672 + 1344

__device__ __constant__ int c_T[4]    = {168, 336, 672, 1344};
__device__ __constant__ int c_Toff[4] = {0, 168, 504, 1176};

// Scratch (device globals — no runtime allocation allowed)
__device__ float g_xs[(size_t)MROWS * INTER];   // 512 MiB intermediate
__device__ float g_w2[(size_t)INTER * TTOT];    // interpolated W_shared^T, [K=4096][TTOT]
__device__ float g_wr[(size_t)EMBED * TTOT];    // interpolated W_res^T,    [K=1024][TTOT]
__device__ float g_b2[TTOT];
__device__ float g_br[TTOT];

// ----------------------------------------------------------------------------
// Kernel 1: build interpolated weights for ALL four patch sizes.
// Matches jnp: src = max((t+0.5)*S/T - 0.5, 0); i0=clip(floor,0,S-1); i1=min(i0+1,S-1)
// Note S/T is an exact power of two for every size -> bit-exact coefficients.
// ----------------------------------------------------------------------------
__global__ void build_weights_kernel(const float* __restrict__ Ws,  // (672,4096)
                                     const float* __restrict__ bs,  // (672,)
                                     const float* __restrict__ Wr,  // (672,1024)
                                     const float* __restrict__ brs) // (672,)
{
    const long n_w2 = (long)INTER * TTOT;
    const long n_wr = (long)EMBED * TTOT;
    const long total = n_w2 + n_wr + 2 * TTOT;
    for (long idx = blockIdx.x * (long)blockDim.x + threadIdx.x; idx < total;
         idx += (long)gridDim.x * blockDim.x) {
        long r = idx;
        int tg, lead;
        const int kind = (r < n_w2) ? 0 : (r < n_w2 + n_wr) ? 1
                       : (r < n_w2 + n_wr + TTOT) ? 2 : 3;
        if (kind == 0)      { tg = (int)(r % TTOT); lead = (int)(r / TTOT); }
        else if (kind == 1) { r -= n_w2; tg = (int)(r % TTOT); lead = (int)(r / TTOT); }
        else if (kind == 2) { tg = (int)(r - n_w2 - n_wr); lead = 0; }
        else                { tg = (int)(r - n_w2 - n_wr - TTOT); lead = 0; }

        const int s = (tg < 168) ? 0 : (tg < 504) ? 1 : (tg < 1176) ? 2 : 3;
        const int t = tg - c_Toff[s];
        const float scale = (float)SBASE / (float)c_T[s];
        float src = fmaxf(((float)t + 0.5f) * scale - 0.5f, 0.0f);
        int i0 = (int)src;                 // src >= 0 so trunc == floor
        if (i0 > SBASE - 1) i0 = SBASE - 1;
        const int i1 = min(i0 + 1, SBASE - 1);
        const float lam = src - (float)i0;

        if (kind == 0) {
            g_w2[idx] = Ws[(long)i0 * INTER + lead] * (1.0f - lam)
                      + Ws[(long)i1 * INTER + lead] * lam;
        } else if (kind == 1) {
            g_wr[(long)lead * TTOT + tg] = Wr[(long)i0 * EMBED + lead] * (1.0f - lam)
                                         + Wr[(long)i1 * EMBED + lead] * lam;
        } else if (kind == 2) {
            g_b2[tg] = bs[i0] * (1.0f - lam) + bs[i1] * lam;
        } else {
            g_br[tg] = brs[i0] * (1.0f - lam) + brs[i1] * lam;
        }
    }
}

// ----------------------------------------------------------------------------
// Kernel 2: GEMM1  g_xs[M=32768][4096] = x[M][1024] @ W_in[4096][1024]^T + b_in
// 128x128x16 tile, 8x8 per thread, 256 threads.
// ----------------------------------------------------------------------------
__global__ __launch_bounds__(256) void gemm_in_kernel(const float* __restrict__ A,
                                                      const float* __restrict__ W,
                                                      const float* __restrict__ bias)
{
    __shared__ __align__(16) float As[16][128];
    __shared__ __align__(16) float Bs[16][128];

    const int bm = blockIdx.y * 128;
    const int bn = blockIdx.x * 128;
    const int tid = threadIdx.x;
    const int arow = tid >> 1;
    const int koff = (tid & 1) << 3;
    const int tx = tid & 15;
    const int ty = tid >> 4;

    const float* Ap = A + (size_t)(bm + arow) * EMBED + koff;
    const float* Wp = W + (size_t)(bn + arow) * EMBED + koff;

    float acc[8][8];
#pragma unroll
    for (int i = 0; i < 8; i++)
#pragma unroll
        for (int j = 0; j < 8; j++) acc[i][j] = 0.0f;

    for (int k0 = 0; k0 < EMBED; k0 += 16) {
        float4 a0 = *(const float4*)(Ap + k0);
        float4 a1 = *(const float4*)(Ap + k0 + 4);
        float4 w0 = *(const float4*)(Wp + k0);
        float4 w1 = *(const float4*)(Wp + k0 + 4);
        As[koff + 0][arow] = a0.x; As[koff + 1][arow] = a0.y;
        As[koff + 2][arow] = a0.z; As[koff + 3][arow] = a0.w;
        As[koff + 4][arow] = a1.x; As[koff + 5][arow] = a1.y;
        As[koff + 6][arow] = a1.z; As[koff + 7][arow] = a1.w;
        Bs[koff + 0][arow] = w0.x; Bs[koff + 1][arow] = w0.y;
        Bs[koff + 2][arow] = w0.z; Bs[koff + 3][arow] = w0.w;
        Bs[koff + 4][arow] = w1.x; Bs[koff + 5][arow] = w1.y;
        Bs[koff + 6][arow] = w1.z; Bs[koff + 7][arow] = w1.w;
        __syncthreads();
#pragma unroll
        for (int kk = 0; kk < 16; kk++) {
            float ar[8], br[8];
            *(float4*)&ar[0] = *(const float4*)&As[kk][ty * 8];
            *(float4*)&ar[4] = *(const float4*)&As[kk][ty * 8 + 4];
            *(float4*)&br[0] = *(const float4*)&Bs[kk][tx * 8];
            *(float4*)&br[4] = *(const float4*)&Bs[kk][tx * 8 + 4];
#pragma unroll
            for (int i = 0; i < 8; i++)
#pragma unroll
                for (int j = 0; j < 8; j++)
                    acc[i][j] = fmaf(ar[i], br[j], acc[i][j]);
        }
        __syncthreads();
    }

    float bv[8];
    *(float4*)&bv[0] = *(const float4*)(bias + bn + tx * 8);
    *(float4*)&bv[4] = *(const float4*)(bias + bn + tx * 8 + 4);
#pragma unroll
    for (int i = 0; i < 8; i++) {
        float* Crow = g_xs + (size_t)(bm + ty * 8 + i) * INTER + bn + tx * 8;
        float4 o0, o1;
        o0.x = acc[i][0] + bv[0]; o0.y = acc[i][1] + bv[1];
        o0.z = acc[i][2] + bv[2]; o0.w = acc[i][3] + bv[3];
        o1.x = acc[i][4] + bv[4]; o1.y = acc[i][5] + bv[5];
        o1.z = acc[i][6] + bv[6]; o1.w = acc[i][7] + bv[7];
        *(float4*)(Crow) = o0;
        *(float4*)(Crow + 4) = o1;
    }
}

// ----------------------------------------------------------------------------
// Kernel 3: fused head. One CTA = (sample n, 128-wide t tile).
//   out[n,p,t] = silu(xs[n,p,:] @ w2_seg + b2) + x[n,p,:] @ wr_seg + br   (t < T[n])
//              = 0                                                        (t >= T[n])
// ----------------------------------------------------------------------------
__global__ __launch_bounds__(256) void head_kernel(const float* __restrict__ x,
                                                   const int* __restrict__ psz,
                                                   float* __restrict__ out,
                                                   int max_dim)
{
    const int n  = blockIdx.y;
    const int t0 = blockIdx.x * 128;
    const int tid = threadIdx.x;

    const int ps = psz[n];
    const int s = (ps == 8) ? 0 : (ps == 16) ? 1 : (ps == 32) ? 2 : 3;
    const int T = ps * OUTD;
    const int toff = c_Toff[s];

    float* outBase = out + (size_t)n * PTOK * max_dim;

    if (t0 >= T) {  // pure zero-pad tile
        const int cols = min(128, max_dim - t0);
        for (int idx = tid; idx < PTOK * cols; idx += 256) {
            const int r = idx / cols, c = idx % cols;
            outBase[(size_t)r * max_dim + t0 + c] = 0.0f;
        }
        return;
    }

    __shared__ __align__(16) float As[16][128];
    __shared__ __align__(16) float Bs[16][128];

    const int arow = tid >> 1;
    const int koff = (tid & 1) << 3;
    const int tx = tid & 15;
    const int ty = tid >> 4;
    const int bcol = (tid & 31) << 2;  // 0..124
    const int bkr  = tid >> 5;         // 0..7

    const int tmax = T - t0;           // valid cols in this tile (may exceed 128)
    const bool fullB = (tmax >= 128);

    float acc[8][8];
#pragma unroll
    for (int i = 0; i < 8; i++)
#pragma unroll
        for (int j = 0; j < 8; j++) acc[i][j] = 0.0f;

    // ---- pass 1: lin = xs @ w2_seg  (K = 4096) ----
    {
        const float* Ap = g_xs + ((size_t)n * PTOK + arow) * INTER + koff;
        const float* Bp = g_w2 + toff + t0;
        for (int k0 = 0; k0 < INTER; k0 += 16) {
            float4 a0 = *(const float4*)(Ap + k0);
            float4 a1 = *(const float4*)(Ap + k0 + 4);
            As[koff + 0][arow] = a0.x; As[koff + 1][arow] = a0.y;
            As[koff + 2][arow] = a0.z; As[koff + 3][arow] = a0.w;
            As[koff + 4][arow] = a1.x; As[koff + 5][arow] = a1.y;
            As[koff + 6][arow] = a1.z; As[koff + 7][arow] = a1.w;
#pragma unroll
            for (int rr = 0; rr < 2; rr++) {
                const int kr = bkr + rr * 8;
                const float* src = Bp + (size_t)(k0 + kr) * TTOT + bcol;
                if (fullB || bcol + 3 < tmax) {
                    float4 v = *(const float4*)src;
                    Bs[kr][bcol] = v.x; Bs[kr][bcol + 1] = v.y;
                    Bs[kr][bcol + 2] = v.z; Bs[kr][bcol + 3] = v.w;
                } else {
#pragma unroll
                    for (int u = 0; u < 4; u++)
                        Bs[kr][bcol + u] = (bcol + u < tmax) ? src[u] : 0.0f;
                }
            }
            __syncthreads();
#pragma unroll
            for (int kk = 0; kk < 16; kk++) {
                float ar[8], br[8];
                *(float4*)&ar[0] = *(const float4*)&As[kk][ty * 8];
                *(float4*)&ar[4] = *(const float4*)&As[kk][ty * 8 + 4];
                *(float4*)&br[0] = *(const float4*)&Bs[kk][tx * 8];
                *(float4*)&br[4] = *(const float4*)&Bs[kk][tx * 8 + 4];
#pragma unroll
                for (int i = 0; i < 8; i++)
#pragma unroll
                    for (int j = 0; j < 8; j++)
                        acc[i][j] = fmaf(ar[i], br[j], acc[i][j]);
            }
            __syncthreads();
        }
    }

    // ---- silu(lin + b2) ----
    {
        float bb[8];
#pragma unroll
        for (int j = 0; j < 8; j++) {
            const int c = t0 + tx * 8 + j;
            bb[j] = (c < T) ? g_b2[toff + c] : 0.0f;
        }
#pragma unroll
        for (int i = 0; i < 8; i++)
#pragma unroll
            for (int j = 0; j < 8; j++) {
                const float v = acc[i][j] + bb[j];
                acc[i][j] = v / (1.0f + __expf(-v));
            }
    }

    // ---- pass 2: += x @ wr_seg  (K = 1024) ----
    {
        const float* Ap = x + ((size_t)n * PTOK + arow) * EMBED + koff;
        const float* Bp = g_wr + toff + t0;
        for (int k0 = 0; k0 < EMBED; k0 += 16) {
            float4 a0 = *(const float4*)(Ap + k0);
            float4 a1 = *(const float4*)(Ap + k0 + 4);
            As[koff + 0][arow] = a0.x; As[koff + 1][arow] = a0.y;
            As[koff + 2][arow] = a0.z; As[koff + 3][arow] = a0.w;
            As[koff + 4][arow] = a1.x; As[koff + 5][arow] = a1.y;
            As[koff + 6][arow] = a1.z; As[koff + 7][arow] = a1.w;
#pragma unroll
            for (int rr = 0; rr < 2; rr++) {
                const int kr = bkr + rr * 8;
                const float* src = Bp + (size_t)(k0 + kr) * TTOT + bcol;
                if (fullB || bcol + 3 < tmax) {
                    float4 v = *(const float4*)src;
                    Bs[kr][bcol] = v.x; Bs[kr][bcol + 1] = v.y;
                    Bs[kr][bcol + 2] = v.z; Bs[kr][bcol + 3] = v.w;
                } else {
#pragma unroll
                    for (int u = 0; u < 4; u++)
                        Bs[kr][bcol + u] = (bcol + u < tmax) ? src[u] : 0.0f;
                }
            }
            __syncthreads();
#pragma unroll
            for (int kk = 0; kk < 16; kk++) {
                float ar[8], br[8];
                *(float4*)&ar[0] = *(const float4*)&As[kk][ty * 8];
                *(float4*)&ar[4] = *(const float4*)&As[kk][ty * 8 + 4];
                *(float4*)&br[0] = *(const float4*)&Bs[kk][tx * 8];
                *(float4*)&br[4] = *(const float4*)&Bs[kk][tx * 8 + 4];
#pragma unroll
                for (int i = 0; i < 8; i++)
#pragma unroll
                    for (int j = 0; j < 8; j++)
                        acc[i][j] = fmaf(ar[i], br[j], acc[i][j]);
            }
            __syncthreads();
        }
    }

    // ---- store: acc + br (valid cols), zeros for T..tile_end ----
    {
        float brv[8];
#pragma unroll
        for (int j = 0; j < 8; j++) {
            const int c = t0 + tx * 8 + j;
            brv[j] = (c < T) ? g_br[toff + c] : 0.0f;
        }
#pragma unroll
        for (int i = 0; i < 8; i++) {
            float* orow = outBase + (size_t)(ty * 8 + i) * max_dim;
#pragma unroll
            for (int j = 0; j < 8; j++) {
                const int c = t0 + tx * 8 + j;
                if (c < max_dim)
                    orow[c] = (c < T) ? (acc[i][j] + brv[j]) : 0.0f;
            }
        }
    }
}

// ----------------------------------------------------------------------------
extern "C" void kernel_launch(void* const* d_in, const int* in_sizes, int n_in,
                              void* d_out, int out_size)
{
    const float* x     = (const float*)d_in[0];
    const int*   psz   = (const int*)d_in[1];
    const float* W_in  = (const float*)d_in[2];
    const float* b_in  = (const float*)d_in[3];
    const float* W_sh  = (const float*)d_in[4];
    const float* b_sh  = (const float*)d_in[5];
    const float* W_res = (const float*)d_in[6];
    const float* b_res = (const float*)d_in[7];
    float* out = (float*)d_out;

    const int max_dim = out_size / (NSAMP * PTOK);

    // 1) interpolated weights for all 4 patch sizes
    build_weights_kernel<<<8192, 256>>>(W_sh, b_sh, W_res, b_res);

    // 2) shared input projection: xs = x @ W_in^T + b_in
    dim3 g1(INTER / 128, MROWS / 128);   // (32, 256)
    gemm_in_kernel<<<g1, 256>>>(x, W_in, b_in);

    // 3) fused per-sample heads + zero padding
    dim3 g3((max_dim + 127) / 128, NSAMP);
    head_kernel<<<g3, 256>>>(x, psz, out, max_dim);
}

// round 4
// speedup vs baseline: 2.4099x; 2.4099x over previous
#include <cuda_runtime.h>
#include <cuda_bf16.h>
#include <math.h>
#include <stdint.h>

// ============================================================================
// MultiSizeProjHead via portable mma.sync (bf16 split, fp32 accum)
// Target is plain sm_103 (no 'a'): tcgen05/TMEM unavailable; HMMA fallback.
//   x:        (256, 128, 1024) f32
//   psizes:   (256,) int32 in {8,16,32,64}
//   W_in:     (4096, 1024), b_in: (4096,)
//   W_shared: (672, 4096),  b_shared: (672,)
//   W_res:    (672, 1024),  b_res: (672,)
//   out:      (256, 128, max_ps*21) f32
// ============================================================================
#define EMBED   1024
#define INTER   4096
#define SBASE   672
#define OUTD    21
#define NSAMP   256
#define PTOK    128
#define MROWS   (NSAMP * PTOK)
#define TTOT    2520        // 168 + 336 + 672 + 1344

#define KC       32                  // K per SMEM stage
#define TSTRIDE  80                  // bytes per smem row: 32 bf16 + 8 pad
#define TILE_B   (128 * TSTRIDE)     // 10240 bytes per 128x32 tile
#define STAGE_B  (4 * TILE_B)        // Ah, Al, Bh, Bl
#define SMEM_TOTAL (2 * STAGE_B)     // double buffered: 81920 B

__device__ __constant__ int c_T[4]    = {168, 336, 672, 1344};
__device__ __constant__ int c_Toff[4] = {0, 168, 504, 1176};

// ---------------- device scratch (no runtime allocation allowed) -----------
__device__ __nv_bfloat16 g_xh [(size_t)MROWS * EMBED];
__device__ __nv_bfloat16 g_xl [(size_t)MROWS * EMBED];
__device__ __nv_bfloat16 g_wih[(size_t)INTER * EMBED];
__device__ __nv_bfloat16 g_wil[(size_t)INTER * EMBED];
__device__ __nv_bfloat16 g_xsh[(size_t)MROWS * INTER];
__device__ __nv_bfloat16 g_xsl[(size_t)MROWS * INTER];
__device__ __nv_bfloat16 g_w2h[(size_t)TTOT * INTER];   // t-major: [t][k]
__device__ __nv_bfloat16 g_w2l[(size_t)TTOT * INTER];
__device__ __nv_bfloat16 g_wrh[(size_t)TTOT * EMBED];
__device__ __nv_bfloat16 g_wrl[(size_t)TTOT * EMBED];
__device__ float g_b2[TTOT];
__device__ float g_br[TTOT];

// ---------------- portable PTX helpers -------------------------------------
__device__ __forceinline__ uint32_t smem_to_u32(const void* p) {
    uint32_t a;
    asm("{ .reg .u64 t; cvta.to.shared.u64 t, %1; cvt.u32.u64 %0, t; }" : "=r"(a) : "l"(p));
    return a;
}
__device__ __forceinline__ void cp_async16(uint32_t dst, const void* src, uint32_t src_bytes) {
    asm volatile("cp.async.cg.shared.global [%0], [%1], 16, %2;"
                 :: "r"(dst), "l"(src), "r"(src_bytes) : "memory");
}
#define CP_COMMIT() asm volatile("cp.async.commit_group;" ::: "memory")
#define CP_WAIT0()  asm volatile("cp.async.wait_group 0;" ::: "memory")

__device__ __forceinline__ void ldsm_x4(uint32_t* r, uint32_t addr) {
    asm volatile("ldmatrix.sync.aligned.m8n8.x4.shared.b16 {%0,%1,%2,%3}, [%4];"
                 : "=r"(r[0]), "=r"(r[1]), "=r"(r[2]), "=r"(r[3]) : "r"(addr));
}
__device__ __forceinline__ void mma16816(float* c, const uint32_t* a, uint32_t b0, uint32_t b1) {
    asm volatile("mma.sync.aligned.m16n8k16.row.col.f32.bf16.bf16.f32 "
                 "{%0,%1,%2,%3}, {%4,%5,%6,%7}, {%8,%9}, {%0,%1,%2,%3};"
                 : "+f"(c[0]), "+f"(c[1]), "+f"(c[2]), "+f"(c[3])
                 : "r"(a[0]), "r"(a[1]), "r"(a[2]), "r"(a[3]), "r"(b0), "r"(b1));
}
__device__ __forceinline__ void split2(float v, __nv_bfloat16& h, __nv_bfloat16& l) {
    h = __float2bfloat16(v);
    l = __float2bfloat16(v - __bfloat162float(h));
}
__device__ __forceinline__ uint32_t pack2(__nv_bfloat16 a, __nv_bfloat16 b) {
    return (uint32_t)__bfloat16_as_ushort(a) | ((uint32_t)__bfloat16_as_ushort(b) << 16);
}

// async-load one 128x32 bf16 tile (rows padded to 80B); rows >= vrows zero-fill
__device__ __forceinline__ void load_tile_async(uint32_t sdst, const __nv_bfloat16* __restrict__ src,
                                                long row0, long stride, int k0, int tid, int vrows) {
#pragma unroll
    for (int i = 0; i < 2; i++) {
        const int c = tid + (i << 8);          // 0..511 chunks of 16B
        const int row = c >> 2, c4 = c & 3;
        const uint32_t d = sdst + (uint32_t)(row * TSTRIDE + c4 * 16);
        const bool ok = (row < vrows);
        const long srow = ok ? (row0 + row) : row0;   // clamp OOB (zfill anyway)
        const void* s = src + srow * stride + k0 + c4 * 8;
        cp_async16(d, s, ok ? 16u : 0u);
    }
}

// one KC=32 stage of split MMA: acc += Ah*Bh + Ah*Bl + Al*Bh
// A tiles: row-major m x k (k contiguous). B tiles: n-major rows, k contiguous
// => plain (non-trans) ldmatrix yields the col-major B fragment directly.
__device__ __forceinline__ void mma_stage(uint32_t base, int lane, int warp_m, int warp_n,
                                          float acc[4][4][4]) {
    const int lr = lane & 7, lg = lane >> 3;
    const int rowSel = ((lg & 1) << 3) + lr;    // 0..15 over lane halves
    const int colHalf = (lg >> 1) << 3;         // k half: 0 or 8
#pragma unroll
    for (int k16 = 0; k16 < KC; k16 += 16) {
        const uint32_t colOff = (uint32_t)((k16 + colHalf) * 2);
        uint32_t ah[4][4], al[4][4], bh[2][4], bl[2][4];
#pragma unroll
        for (int i = 0; i < 4; i++) {
            const uint32_t addr = base + (uint32_t)((warp_m * 64 + i * 16 + rowSel) * TSTRIDE) + colOff;
            ldsm_x4(ah[i], addr);
            ldsm_x4(al[i], addr + TILE_B);
        }
#pragma unroll
        for (int jj = 0; jj < 2; jj++) {
            const uint32_t addr = base + 2 * TILE_B +
                (uint32_t)((warp_n * 32 + jj * 16 + rowSel) * TSTRIDE) + colOff;
            ldsm_x4(bh[jj], addr);
            ldsm_x4(bl[jj], addr + TILE_B);
        }
#pragma unroll
        for (int i = 0; i < 4; i++)
#pragma unroll
            for (int j = 0; j < 4; j++)
                mma16816(acc[i][j], ah[i], bh[j >> 1][j & 1], bh[j >> 1][(j & 1) + 2]);
#pragma unroll
        for (int i = 0; i < 4; i++)
#pragma unroll
            for (int j = 0; j < 4; j++)
                mma16816(acc[i][j], ah[i], bl[j >> 1][j & 1], bl[j >> 1][(j & 1) + 2]);
#pragma unroll
        for (int i = 0; i < 4; i++)
#pragma unroll
            for (int j = 0; j < 4; j++)
                mma16816(acc[i][j], al[i], bh[j >> 1][j & 1], bh[j >> 1][(j & 1) + 2]);
    }
}

// ---------------- prep kernel 1: split x, W_in into bf16 hi/lo -------------
__global__ void split_inputs_kernel(const float* __restrict__ x, const float* __restrict__ W_in) {
    const long nx = (long)MROWS * EMBED;
    const long nw = (long)INTER * EMBED;
    const long i = blockIdx.x * (long)blockDim.x + threadIdx.x;
    if (i >= nx + nw) return;
    float v; __nv_bfloat16 *ph, *pl; long j;
    if (i < nx) { j = i;      v = x[j];    ph = g_xh;  pl = g_xl;  }
    else        { j = i - nx; v = W_in[j]; ph = g_wih; pl = g_wil; }
    split2(v, ph[j], pl[j]);
}

// ---------------- prep kernel 2: interpolated head weights (t-major) -------
__device__ __forceinline__ void interp_coef(int tg, int& i0, int& i1, float& lam) {
    const int s = (tg < 168) ? 0 : (tg < 504) ? 1 : (tg < 1176) ? 2 : 3;
    const int t = tg - c_Toff[s];
    const float scale = (float)SBASE / (float)c_T[s];
    float src = fmaxf(((float)t + 0.5f) * scale - 0.5f, 0.0f);
    i0 = (int)src;                  // src >= 0 -> trunc == floor
    if (i0 > SBASE - 1) i0 = SBASE - 1;
    i1 = min(i0 + 1, SBASE - 1);
    lam = src - (float)i0;
}

__global__ void build_weights_kernel(const float* __restrict__ Ws, const float* __restrict__ bs,
                                     const float* __restrict__ Wr, const float* __restrict__ brs) {
    const long n2 = (long)TTOT * INTER;
    const long nr = (long)TTOT * EMBED;
    const long total = n2 + nr + 2 * TTOT;
    const long i = blockIdx.x * (long)blockDim.x + threadIdx.x;
    if (i >= total) return;
    int i0, i1; float lam;
    if (i < n2) {
        const int t = (int)(i / INTER), k = (int)(i % INTER);
        interp_coef(t, i0, i1, lam);
        const float v = Ws[(long)i0 * INTER + k] * (1.0f - lam) + Ws[(long)i1 * INTER + k] * lam;
        split2(v, g_w2h[i], g_w2l[i]);
    } else if (i < n2 + nr) {
        const long j = i - n2;
        const int t = (int)(j / EMBED), k = (int)(j % EMBED);
        interp_coef(t, i0, i1, lam);
        const float v = Wr[(long)i0 * EMBED + k] * (1.0f - lam) + Wr[(long)i1 * EMBED + k] * lam;
        split2(v, g_wrh[j], g_wrl[j]);
    } else if (i < n2 + nr + TTOT) {
        const int t = (int)(i - n2 - nr);
        interp_coef(t, i0, i1, lam);
        g_b2[t] = bs[i0] * (1.0f - lam) + bs[i1] * lam;
    } else {
        const int t = (int)(i - n2 - nr - TTOT);
        interp_coef(t, i0, i1, lam);
        g_br[t] = brs[i0] * (1.0f - lam) + brs[i1] * lam;
    }
}

// ---------------- GEMM1: xs = x @ W_in^T + b_in ------------------------------
__global__ void __launch_bounds__(256)
gemm1_kernel(const float* __restrict__ b_in) {
    extern __shared__ char smem[];
    const uint32_t sb = smem_to_u32(smem);
    const int tid = threadIdx.x;
    const int lane = tid & 31, wid = tid >> 5;
    const int warp_m = wid >> 2, warp_n = wid & 3;
    const long bm = (long)blockIdx.y * 128;
    const long bn = (long)blockIdx.x * 128;

    float acc[4][4][4];
#pragma unroll
    for (int i = 0; i < 4; i++)
#pragma unroll
        for (int j = 0; j < 4; j++)
#pragma unroll
            for (int e = 0; e < 4; e++) acc[i][j][e] = 0.0f;

    // stage 0
    {
        const uint32_t base = sb;
        load_tile_async(base,              g_xh,  bm, EMBED, 0, tid, 128);
        load_tile_async(base + TILE_B,     g_xl,  bm, EMBED, 0, tid, 128);
        load_tile_async(base + 2 * TILE_B, g_wih, bn, EMBED, 0, tid, 128);
        load_tile_async(base + 3 * TILE_B, g_wil, bn, EMBED, 0, tid, 128);
        CP_COMMIT();
    }
    const int nK = EMBED / KC;
    for (int ks = 0; ks < nK; ks++) {
        CP_WAIT0();
        __syncthreads();
        if (ks + 1 < nK) {
            const uint32_t base = sb + ((ks + 1) & 1) * STAGE_B;
            const int k0 = (ks + 1) * KC;
            load_tile_async(base,              g_xh,  bm, EMBED, k0, tid, 128);
            load_tile_async(base + TILE_B,     g_xl,  bm, EMBED, k0, tid, 128);
            load_tile_async(base + 2 * TILE_B, g_wih, bn, EMBED, k0, tid, 128);
            load_tile_async(base + 3 * TILE_B, g_wil, bn, EMBED, k0, tid, 128);
            CP_COMMIT();
        }
        mma_stage(sb + (ks & 1) * STAGE_B, lane, warp_m, warp_n, acc);
    }

    // epilogue: +b_in, split to bf16 hi/lo, store
    const int r0 = lane >> 2;
    const int c0 = (lane & 3) * 2;
#pragma unroll
    for (int i = 0; i < 4; i++) {
        const long rowA = bm + warp_m * 64 + i * 16 + r0;
        const long rowB = rowA + 8;
#pragma unroll
        for (int j = 0; j < 4; j++) {
            const long col = bn + warp_n * 32 + j * 8 + c0;
            const float bi0 = b_in[col], bi1 = b_in[col + 1];
            __nv_bfloat16 h0, l0, h1, l1;
            split2(acc[i][j][0] + bi0, h0, l0);
            split2(acc[i][j][1] + bi1, h1, l1);
            *(uint32_t*)(g_xsh + rowA * INTER + col) = pack2(h0, h1);
            *(uint32_t*)(g_xsl + rowA * INTER + col) = pack2(l0, l1);
            split2(acc[i][j][2] + bi0, h0, l0);
            split2(acc[i][j][3] + bi1, h1, l1);
            *(uint32_t*)(g_xsh + rowB * INTER + col) = pack2(h0, h1);
            *(uint32_t*)(g_xsl + rowB * INTER + col) = pack2(l0, l1);
        }
    }
}

// ---------------- head kernel: silu(xs@w2+b2) + x@wr+br + padding ----------
__global__ void __launch_bounds__(256)
head_kernel(const int* __restrict__ psz, float* __restrict__ out, int max_dim) {
    const int n  = blockIdx.y;
    const int t0 = blockIdx.x * 128;
    const int tid = threadIdx.x;

    const int ps = psz[n];
    const int T = ps * OUTD;
    const int s4 = (ps == 8) ? 0 : (ps == 16) ? 1 : (ps == 32) ? 2 : 3;
    const int toff = c_Toff[s4];
    float* outBase = out + (size_t)n * PTOK * max_dim;

    if (t0 >= T) {  // pure zero-pad tile
        const int colq = min(128, max_dim - t0) >> 2;
        const float4 z = make_float4(0.f, 0.f, 0.f, 0.f);
        for (int idx = tid; idx < PTOK * colq; idx += 256) {
            const int r = idx / colq, c = idx % colq;
            *reinterpret_cast<float4*>(outBase + (size_t)r * max_dim + t0 + c * 4) = z;
        }
        return;
    }

    extern __shared__ char smem[];
    const uint32_t sb = smem_to_u32(smem);
    const int lane = tid & 31, wid = tid >> 5;
    const int warp_m = wid >> 2, warp_n = wid & 3;

    const int tmax = min(T - t0, 128);
    const long arow = (long)n * PTOK;
    const long brow = (long)toff + t0;

    float acc[4][4][4];
#pragma unroll
    for (int i = 0; i < 4; i++)
#pragma unroll
        for (int j = 0; j < 4; j++)
#pragma unroll
            for (int e = 0; e < 4; e++) acc[i][j][e] = 0.0f;

    const int r0 = lane >> 2;
    const int c0 = (lane & 3) * 2;

    // ---- pass 1: lin = xs @ w2_seg^T  (K = 4096) ----
    {
        const uint32_t base = sb;
        load_tile_async(base,              g_xsh, arow, INTER, 0, tid, 128);
        load_tile_async(base + TILE_B,     g_xsl, arow, INTER, 0, tid, 128);
        load_tile_async(base + 2 * TILE_B, g_w2h, brow, INTER, 0, tid, tmax);
        load_tile_async(base + 3 * TILE_B, g_w2l, brow, INTER, 0, tid, tmax);
        CP_COMMIT();
    }
    const int nK1 = INTER / KC;
    for (int ks = 0; ks < nK1; ks++) {
        CP_WAIT0();
        __syncthreads();
        if (ks + 1 < nK1) {
            const uint32_t base = sb + ((ks + 1) & 1) * STAGE_B;
            const int k0 = (ks + 1) * KC;
            load_tile_async(base,              g_xsh, arow, INTER, k0, tid, 128);
            load_tile_async(base + TILE_B,     g_xsl, arow, INTER, k0, tid, 128);
            load_tile_async(base + 2 * TILE_B, g_w2h, brow, INTER, k0, tid, tmax);
            load_tile_async(base + 3 * TILE_B, g_w2l, brow, INTER, k0, tid, tmax);
            CP_COMMIT();
        }
        mma_stage(sb + (ks & 1) * STAGE_B, lane, warp_m, warp_n, acc);
    }

    // ---- silu(lin + b2) in registers ----
#pragma unroll
    for (int j = 0; j < 4; j++) {
        const int col = t0 + warp_n * 32 + j * 8 + c0;
        const float b20 = (col     < T) ? g_b2[toff + col]     : 0.0f;
        const float b21 = (col + 1 < T) ? g_b2[toff + col + 1] : 0.0f;
#pragma unroll
        for (int i = 0; i < 4; i++) {
            float v;
            v = acc[i][j][0] + b20; acc[i][j][0] = v / (1.0f + __expf(-v));
            v = acc[i][j][1] + b21; acc[i][j][1] = v / (1.0f + __expf(-v));
            v = acc[i][j][2] + b20; acc[i][j][2] = v / (1.0f + __expf(-v));
            v = acc[i][j][3] + b21; acc[i][j][3] = v / (1.0f + __expf(-v));
        }
    }

    // ---- pass 2: acc += x @ wr_seg^T  (K = 1024) ----
    {
        const uint32_t base = sb;
        load_tile_async(base,              g_xh,  arow, EMBED, 0, tid, 128);
        load_tile_async(base + TILE_B,     g_xl,  arow, EMBED, 0, tid, 128);
        load_tile_async(base + 2 * TILE_B, g_wrh, brow, EMBED, 0, tid, tmax);
        load_tile_async(base + 3 * TILE_B, g_wrl, brow, EMBED, 0, tid, tmax);
        CP_COMMIT();
    }
    const int nK2 = EMBED / KC;
    for (int ks = 0; ks < nK2; ks++) {
        CP_WAIT0();
        __syncthreads();
        if (ks + 1 < nK2) {
            const uint32_t base = sb + ((ks + 1) & 1) * STAGE_B;
            const int k0 = (ks + 1) * KC;
            load_tile_async(base,              g_xh,  arow, EMBED, k0, tid, 128);
            load_tile_async(base + TILE_B,     g_xl,  arow, EMBED, k0, tid, 128);
            load_tile_async(base + 2 * TILE_B, g_wrh, brow, EMBED, k0, tid, tmax);
            load_tile_async(base + 3 * TILE_B, g_wrl, brow, EMBED, k0, tid, tmax);
            CP_COMMIT();
        }
        mma_stage(sb + (ks & 1) * STAGE_B, lane, warp_m, warp_n, acc);
    }

    // ---- store: acc + br (cols < T), zeros to max_dim ----
#pragma unroll
    for (int i = 0; i < 4; i++) {
        const int rowA = warp_m * 64 + i * 16 + r0;
#pragma unroll
        for (int j = 0; j < 4; j++) {
            const int col = t0 + warp_n * 32 + j * 8 + c0;
            if (col >= max_dim) continue;
            float2 v0, v1;
            if (col < T) {   // T even, col even -> col+1 < T too
                const float br0 = g_br[toff + col], br1 = g_br[toff + col + 1];
                v0 = make_float2(acc[i][j][0] + br0, acc[i][j][1] + br1);
                v1 = make_float2(acc[i][j][2] + br0, acc[i][j][3] + br1);
            } else {
                v0 = make_float2(0.f, 0.f);
                v1 = v0;
            }
            *reinterpret_cast<float2*>(outBase + (size_t)rowA * max_dim + col) = v0;
            *reinterpret_cast<float2*>(outBase + (size_t)(rowA + 8) * max_dim + col) = v1;
        }
    }
}

// ----------------------------------------------------------------------------
extern "C" void kernel_launch(void* const* d_in, const int* in_sizes, int n_in,
                              void* d_out, int out_size)
{
    const float* x     = (const float*)d_in[0];
    const int*   psz   = (const int*)d_in[1];
    const float* W_in  = (const float*)d_in[2];
    const float* b_in  = (const float*)d_in[3];
    const float* W_sh  = (const float*)d_in[4];
    const float* b_sh  = (const float*)d_in[5];
    const float* W_res = (const float*)d_in[6];
    const float* b_res = (const float*)d_in[7];
    float* out = (float*)d_out;

    const int max_dim = out_size / (NSAMP * PTOK);

    cudaFuncSetAttribute(gemm1_kernel, cudaFuncAttributeMaxDynamicSharedMemorySize, SMEM_TOTAL);
    cudaFuncSetAttribute(head_kernel,  cudaFuncAttributeMaxDynamicSharedMemorySize, SMEM_TOTAL);

    // 1) split x / W_in into bf16 hi/lo
    {
        const long total = (long)MROWS * EMBED + (long)INTER * EMBED;
        split_inputs_kernel<<<(unsigned)((total + 255) / 256), 256>>>(x, W_in);
    }
    // 2) interpolated head weights (bf16 hi/lo, t-major) + fp32 biases
    {
        const long total = (long)TTOT * INTER + (long)TTOT * EMBED + 2L * TTOT;
        build_weights_kernel<<<(unsigned)((total + 255) / 256), 256>>>(W_sh, b_sh, W_res, b_res);
    }
    // 3) xs = x @ W_in^T + b_in
    {
        dim3 g(INTER / 128, MROWS / 128);   // (32, 256)
        gemm1_kernel<<<g, 256, SMEM_TOTAL>>>(b_in);
    }
    // 4) fused per-sample heads + zero padding
    {
        dim3 g((max_dim + 127) / 128, NSAMP);
        head_kernel<<<g, 256, SMEM_TOTAL>>>(psz, out, max_dim);
    }
}

// round 5
// speedup vs baseline: 2.4159x; 1.0025x over previous
#include <cuda_runtime.h>
#include <cuda_bf16.h>
#include <math.h>
#include <stdint.h>

// ============================================================================
// MultiSizeProjHead via portable mma.sync (bf16 split, fp32 accum)
// Target is plain sm_103 (no 'a'): tcgen05/TMEM unavailable; HMMA fallback.
//   x:        (256, 128, 1024) f32
//   psizes:   (256,) int32 in {8,16,32,64}
//   W_in:     (4096, 1024), b_in: (4096,)
//   W_shared: (672, 4096),  b_shared: (672,)
//   W_res:    (672, 1024),  b_res: (672,)
//   out:      (256, 128, max_ps*21) f32
// ============================================================================
#define EMBED   1024
#define INTER   4096
#define SBASE   672
#define OUTD    21
#define NSAMP   256
#define PTOK    128
#define MROWS   (NSAMP * PTOK)
#define TTOT    2520        // 168 + 336 + 672 + 1344

#define KC       32                  // K per SMEM stage
#define TSTRIDE  80                  // bytes per smem row: 32 bf16 + 8 pad
#define TILE_B   (128 * TSTRIDE)     // 10240 bytes per 128x32 tile
#define STAGE_B  (4 * TILE_B)        // Ah, Al, Bh, Bl
#define SMEM_TOTAL (2 * STAGE_B)     // double buffered: 81920 B

__device__ __constant__ int c_T[4]    = {168, 336, 672, 1344};
__device__ __constant__ int c_Toff[4] = {0, 168, 504, 1176};

// ---------------- device scratch (no runtime allocation allowed) -----------
__device__ __nv_bfloat16 g_xh [(size_t)MROWS * EMBED];
__device__ __nv_bfloat16 g_xl [(size_t)MROWS * EMBED];
__device__ __nv_bfloat16 g_wih[(size_t)INTER * EMBED];
__device__ __nv_bfloat16 g_wil[(size_t)INTER * EMBED];
__device__ __nv_bfloat16 g_xsh[(size_t)MROWS * INTER];
__device__ __nv_bfloat16 g_xsl[(size_t)MROWS * INTER];
__device__ __nv_bfloat16 g_w2h[(size_t)TTOT * INTER];   // t-major: [t][k]
__device__ __nv_bfloat16 g_w2l[(size_t)TTOT * INTER];
__device__ __nv_bfloat16 g_wrh[(size_t)TTOT * EMBED];
__device__ __nv_bfloat16 g_wrl[(size_t)TTOT * EMBED];
__device__ float g_b2[TTOT];
__device__ float g_br[TTOT];

// ---------------- portable PTX helpers -------------------------------------
__device__ __forceinline__ uint32_t smem_to_u32(const void* p) {
    uint32_t a;
    asm("{ .reg .u64 t; cvta.to.shared.u64 t, %1; cvt.u32.u64 %0, t; }" : "=r"(a) : "l"(p));
    return a;
}
__device__ __forceinline__ void cp_async16(uint32_t dst, const void* src, uint32_t src_bytes) {
    asm volatile("cp.async.cg.shared.global [%0], [%1], 16, %2;"
                 :: "r"(dst), "l"(src), "r"(src_bytes) : "memory");
}
#define CP_COMMIT() asm volatile("cp.async.commit_group;" ::: "memory")
#define CP_WAIT0()  asm volatile("cp.async.wait_group 0;" ::: "memory")

__device__ __forceinline__ void ldsm_x4(uint32_t* r, uint32_t addr) {
    asm volatile("ldmatrix.sync.aligned.m8n8.x4.shared.b16 {%0,%1,%2,%3}, [%4];"
                 : "=r"(r[0]), "=r"(r[1]), "=r"(r[2]), "=r"(r[3]) : "r"(addr));
}
__device__ __forceinline__ void mma16816(float* c, const uint32_t* a, uint32_t b0, uint32_t b1) {
    asm volatile("mma.sync.aligned.m16n8k16.row.col.f32.bf16.bf16.f32 "
                 "{%0,%1,%2,%3}, {%4,%5,%6,%7}, {%8,%9}, {%0,%1,%2,%3};"
                 : "+f"(c[0]), "+f"(c[1]), "+f"(c[2]), "+f"(c[3])
                 : "r"(a[0]), "r"(a[1]), "r"(a[2]), "r"(a[3]), "r"(b0), "r"(b1));
}
__device__ __forceinline__ void split2(float v, __nv_bfloat16& h, __nv_bfloat16& l) {
    h = __float2bfloat16(v);
    l = __float2bfloat16(v - __bfloat162float(h));
}
__device__ __forceinline__ uint32_t pack2(__nv_bfloat16 a, __nv_bfloat16 b) {
    return (uint32_t)__bfloat16_as_ushort(a) | ((uint32_t)__bfloat16_as_ushort(b) << 16);
}

// async-load one 128x32 bf16 tile (rows padded to 80B); rows >= vrows zero-fill
__device__ __forceinline__ void load_tile_async(uint32_t sdst, const __nv_bfloat16* __restrict__ src,
                                                long row0, long stride, int k0, int tid, int vrows) {
#pragma unroll
    for (int i = 0; i < 2; i++) {
        const int c = tid + (i << 8);          // 0..511 chunks of 16B
        const int row = c >> 2, c4 = c & 3;
        const uint32_t d = sdst + (uint32_t)(row * TSTRIDE + c4 * 16);
        const bool ok = (row < vrows);
        const long srow = ok ? (row0 + row) : row0;   // clamp OOB (zfill anyway)
        const void* s = src + srow * stride + k0 + c4 * 8;
        cp_async16(d, s, ok ? 16u : 0u);
    }
}

// one KC=32 stage of split MMA: acc += Ah*Bh + Ah*Bl + Al*Bh
// A tiles: row-major m x k (k contiguous). B tiles: n-major rows, k contiguous
// => plain (non-trans) ldmatrix yields the col-major B fragment directly.
__device__ __forceinline__ void mma_stage(uint32_t base, int lane, int warp_m, int warp_n,
                                          float acc[4][4][4]) {
    const int lr = lane & 7, lg = lane >> 3;
    const int rowSel = ((lg & 1) << 3) + lr;    // 0..15 over lane halves
    const int colHalf = (lg >> 1) << 3;         // k half: 0 or 8
#pragma unroll
    for (int k16 = 0; k16 < KC; k16 += 16) {
        const uint32_t colOff = (uint32_t)((k16 + colHalf) * 2);
        uint32_t ah[4][4], al[4][4], bh[2][4], bl[2][4];
#pragma unroll
        for (int i = 0; i < 4; i++) {
            const uint32_t addr = base + (uint32_t)((warp_m * 64 + i * 16 + rowSel) * TSTRIDE) + colOff;
            ldsm_x4(ah[i], addr);
            ldsm_x4(al[i], addr + TILE_B);
        }
#pragma unroll
        for (int jj = 0; jj < 2; jj++) {
            const uint32_t addr = base + 2 * TILE_B +
                (uint32_t)((warp_n * 32 + jj * 16 + rowSel) * TSTRIDE) + colOff;
            ldsm_x4(bh[jj], addr);
            ldsm_x4(bl[jj], addr + TILE_B);
        }
#pragma unroll
        for (int i = 0; i < 4; i++)
#pragma unroll
            for (int j = 0; j < 4; j++)
                mma16816(acc[i][j], ah[i], bh[j >> 1][j & 1], bh[j >> 1][(j & 1) + 2]);
#pragma unroll
        for (int i = 0; i < 4; i++)
#pragma unroll
            for (int j = 0; j < 4; j++)
                mma16816(acc[i][j], ah[i], bl[j >> 1][j & 1], bl[j >> 1][(j & 1) + 2]);
#pragma unroll
        for (int i = 0; i < 4; i++)
#pragma unroll
            for (int j = 0; j < 4; j++)
                mma16816(acc[i][j], al[i], bh[j >> 1][j & 1], bh[j >> 1][(j & 1) + 2]);
    }
}

// ---------------- prep kernel 1: split x, W_in into bf16 hi/lo -------------
__global__ void split_inputs_kernel(const float* __restrict__ x, const float* __restrict__ W_in) {
    const long nx = (long)MROWS * EMBED;
    const long nw = (long)INTER * EMBED;
    const long i = blockIdx.x * (long)blockDim.x + threadIdx.x;
    if (i >= nx + nw) return;
    float v; __nv_bfloat16 *ph, *pl; long j;
    if (i < nx) { j = i;      v = x[j];    ph = g_xh;  pl = g_xl;  }
    else        { j = i - nx; v = W_in[j]; ph = g_wih; pl = g_wil; }
    split2(v, ph[j], pl[j]);
}

// ---------------- prep kernel 2: interpolated head weights (t-major) -------
__device__ __forceinline__ void interp_coef(int tg, int& i0, int& i1, float& lam) {
    const int s = (tg < 168) ? 0 : (tg < 504) ? 1 : (tg < 1176) ? 2 : 3;
    const int t = tg - c_Toff[s];
    const float scale = (float)SBASE / (float)c_T[s];
    float src = fmaxf(((float)t + 0.5f) * scale - 0.5f, 0.0f);
    i0 = (int)src;                  // src >= 0 -> trunc == floor
    if (i0 > SBASE - 1) i0 = SBASE - 1;
    i1 = min(i0 + 1, SBASE - 1);
    lam = src - (float)i0;
}

__global__ void build_weights_kernel(const float* __restrict__ Ws, const float* __restrict__ bs,
                                     const float* __restrict__ Wr, const float* __restrict__ brs) {
    const long n2 = (long)TTOT * INTER;
    const long nr = (long)TTOT * EMBED;
    const long total = n2 + nr + 2 * TTOT;
    const long i = blockIdx.x * (long)blockDim.x + threadIdx.x;
    if (i >= total) return;
    int i0, i1; float lam;
    if (i < n2) {
        const int t = (int)(i / INTER), k = (int)(i % INTER);
        interp_coef(t, i0, i1, lam);
        const float v = Ws[(long)i0 * INTER + k] * (1.0f - lam) + Ws[(long)i1 * INTER + k] * lam;
        split2(v, g_w2h[i], g_w2l[i]);
    } else if (i < n2 + nr) {
        const long j = i - n2;
        const int t = (int)(j / EMBED), k = (int)(j % EMBED);
        interp_coef(t, i0, i1, lam);
        const float v = Wr[(long)i0 * EMBED + k] * (1.0f - lam) + Wr[(long)i1 * EMBED + k] * lam;
        split2(v, g_wrh[j], g_wrl[j]);
    } else if (i < n2 + nr + TTOT) {
        const int t = (int)(i - n2 - nr);
        interp_coef(t, i0, i1, lam);
        g_b2[t] = bs[i0] * (1.0f - lam) + bs[i1] * lam;
    } else {
        const int t = (int)(i - n2 - nr - TTOT);
        interp_coef(t, i0, i1, lam);
        g_br[t] = brs[i0] * (1.0f - lam) + brs[i1] * lam;
    }
}

// ---------------- GEMM1: xs = x @ W_in^T + b_in ------------------------------
__global__ void __launch_bounds__(256)
gemm1_kernel(const float* __restrict__ b_in) {
    extern __shared__ char smem[];
    const uint32_t sb = smem_to_u32(smem);
    const int tid = threadIdx.x;
    const int lane = tid & 31, wid = tid >> 5;
    const int warp_m = wid >> 2, warp_n = wid & 3;
    const long bm = (long)blockIdx.y * 128;
    const long bn = (long)blockIdx.x * 128;

    float acc[4][4][4];
#pragma unroll
    for (int i = 0; i < 4; i++)
#pragma unroll
        for (int j = 0; j < 4; j++)
#pragma unroll
            for (int e = 0; e < 4; e++) acc[i][j][e] = 0.0f;

    // stage 0
    {
        const uint32_t base = sb;
        load_tile_async(base,              g_xh,  bm, EMBED, 0, tid, 128);
        load_tile_async(base + TILE_B,     g_xl,  bm, EMBED, 0, tid, 128);
        load_tile_async(base + 2 * TILE_B, g_wih, bn, EMBED, 0, tid, 128);
        load_tile_async(base + 3 * TILE_B, g_wil, bn, EMBED, 0, tid, 128);
        CP_COMMIT();
    }
    const int nK = EMBED / KC;
    for (int ks = 0; ks < nK; ks++) {
        CP_WAIT0();
        __syncthreads();
        if (ks + 1 < nK) {
            const uint32_t base = sb + ((ks + 1) & 1) * STAGE_B;
            const int k0 = (ks + 1) * KC;
            load_tile_async(base,              g_xh,  bm, EMBED, k0, tid, 128);
            load_tile_async(base + TILE_B,     g_xl,  bm, EMBED, k0, tid, 128);
            load_tile_async(base + 2 * TILE_B, g_wih, bn, EMBED, k0, tid, 128);
            load_tile_async(base + 3 * TILE_B, g_wil, bn, EMBED, k0, tid, 128);
            CP_COMMIT();
        }
        mma_stage(sb + (ks & 1) * STAGE_B, lane, warp_m, warp_n, acc);
    }

    // epilogue: +b_in, split to bf16 hi/lo, store
    const int r0 = lane >> 2;
    const int c0 = (lane & 3) * 2;
#pragma unroll
    for (int i = 0; i < 4; i++) {
        const long rowA = bm + warp_m * 64 + i * 16 + r0;
        const long rowB = rowA + 8;
#pragma unroll
        for (int j = 0; j < 4; j++) {
            const long col = bn + warp_n * 32 + j * 8 + c0;
            const float bi0 = b_in[col], bi1 = b_in[col + 1];
            __nv_bfloat16 h0, l0, h1, l1;
            split2(acc[i][j][0] + bi0, h0, l0);
            split2(acc[i][j][1] + bi1, h1, l1);
            *(uint32_t*)(g_xsh + rowA * INTER + col) = pack2(h0, h1);
            *(uint32_t*)(g_xsl + rowA * INTER + col) = pack2(l0, l1);
            split2(acc[i][j][2] + bi0, h0, l0);
            split2(acc[i][j][3] + bi1, h1, l1);
            *(uint32_t*)(g_xsh + rowB * INTER + col) = pack2(h0, h1);
            *(uint32_t*)(g_xsl + rowB * INTER + col) = pack2(l0, l1);
        }
    }
}

// ---------------- head kernel: silu(xs@w2+b2) + x@wr+br + padding ----------
__global__ void __launch_bounds__(256)
head_kernel(const int* __restrict__ psz, float* __restrict__ out, int max_dim) {
    const int n  = blockIdx.y;
    const int t0 = blockIdx.x * 128;
    const int tid = threadIdx.x;

    const int ps = psz[n];
    const int T = ps * OUTD;
    const int s4 = (ps == 8) ? 0 : (ps == 16) ? 1 : (ps == 32) ? 2 : 3;
    const int toff = c_Toff[s4];
    float* outBase = out + (size_t)n * PTOK * max_dim;

    if (t0 >= T) {  // pure zero-pad tile
        const int colq = min(128, max_dim - t0) >> 2;
        const float4 z = make_float4(0.f, 0.f, 0.f, 0.f);
        for (int idx = tid; idx < PTOK * colq; idx += 256) {
            const int r = idx / colq, c = idx % colq;
            *reinterpret_cast<float4*>(outBase + (size_t)r * max_dim + t0 + c * 4) = z;
        }
        return;
    }

    extern __shared__ char smem[];
    const uint32_t sb = smem_to_u32(smem);
    const int lane = tid & 31, wid = tid >> 5;
    const int warp_m = wid >> 2, warp_n = wid & 3;

    const int tmax = min(T - t0, 128);
    const long arow = (long)n * PTOK;
    const long brow = (long)toff + t0;

    float acc[4][4][4];
#pragma unroll
    for (int i = 0; i < 4; i++)
#pragma unroll
        for (int j = 0; j < 4; j++)
#pragma unroll
            for (int e = 0; e < 4; e++) acc[i][j][e] = 0.0f;

    const int r0 = lane >> 2;
    const int c0 = (lane & 3) * 2;

    // ---- pass 1: lin = xs @ w2_seg^T  (K = 4096) ----
    {
        const uint32_t base = sb;
        load_tile_async(base,              g_xsh, arow, INTER, 0, tid, 128);
        load_tile_async(base + TILE_B,     g_xsl, arow, INTER, 0, tid, 128);
        load_tile_async(base + 2 * TILE_B, g_w2h, brow, INTER, 0, tid, tmax);
        load_tile_async(base + 3 * TILE_B, g_w2l, brow, INTER, 0, tid, tmax);
        CP_COMMIT();
    }
    const int nK1 = INTER / KC;
    for (int ks = 0; ks < nK1; ks++) {
        CP_WAIT0();
        __syncthreads();
        if (ks + 1 < nK1) {
            const uint32_t base = sb + ((ks + 1) & 1) * STAGE_B;
            const int k0 = (ks + 1) * KC;
            load_tile_async(base,              g_xsh, arow, INTER, k0, tid, 128);
            load_tile_async(base + TILE_B,     g_xsl, arow, INTER, k0, tid, 128);
            load_tile_async(base + 2 * TILE_B, g_w2h, brow, INTER, k0, tid, tmax);
            load_tile_async(base + 3 * TILE_B, g_w2l, brow, INTER, k0, tid, tmax);
            CP_COMMIT();
        }
        mma_stage(sb + (ks & 1) * STAGE_B, lane, warp_m, warp_n, acc);
    }

    // ---- silu(lin + b2) in registers ----
#pragma unroll
    for (int j = 0; j < 4; j++) {
        const int col = t0 + warp_n * 32 + j * 8 + c0;
        const float b20 = (col     < T) ? g_b2[toff + col]     : 0.0f;
        const float b21 = (col + 1 < T) ? g_b2[toff + col + 1] : 0.0f;
#pragma unroll
        for (int i = 0; i < 4; i++) {
            float v;
            v = acc[i][j][0] + b20; acc[i][j][0] = v / (1.0f + __expf(-v));
            v = acc[i][j][1] + b21; acc[i][j][1] = v / (1.0f + __expf(-v));
            v = acc[i][j][2] + b20; acc[i][j][2] = v / (1.0f + __expf(-v));
            v = acc[i][j][3] + b21; acc[i][j][3] = v / (1.0f + __expf(-v));
        }
    }

    // ---- pass 2: acc += x @ wr_seg^T  (K = 1024) ----
    {
        const uint32_t base = sb;
        load_tile_async(base,              g_xh,  arow, EMBED, 0, tid, 128);
        load_tile_async(base + TILE_B,     g_xl,  arow, EMBED, 0, tid, 128);
        load_tile_async(base + 2 * TILE_B, g_wrh, brow, EMBED, 0, tid, tmax);
        load_tile_async(base + 3 * TILE_B, g_wrl, brow, EMBED, 0, tid, tmax);
        CP_COMMIT();
    }
    const int nK2 = EMBED / KC;
    for (int ks = 0; ks < nK2; ks++) {
        CP_WAIT0();
        __syncthreads();
        if (ks + 1 < nK2) {
            const uint32_t base = sb + ((ks + 1) & 1) * STAGE_B;
            const int k0 = (ks + 1) * KC;
            load_tile_async(base,              g_xh,  arow, EMBED, k0, tid, 128);
            load_tile_async(base + TILE_B,     g_xl,  arow, EMBED, k0, tid, 128);
            load_tile_async(base + 2 * TILE_B, g_wrh, brow, EMBED, k0, tid, tmax);
            load_tile_async(base + 3 * TILE_B, g_wrl, brow, EMBED, k0, tid, tmax);
            CP_COMMIT();
        }
        mma_stage(sb + (ks & 1) * STAGE_B, lane, warp_m, warp_n, acc);
    }

    // ---- store: acc + br (cols < T), zeros to max_dim ----
#pragma unroll
    for (int i = 0; i < 4; i++) {
        const int rowA = warp_m * 64 + i * 16 + r0;
#pragma unroll
        for (int j = 0; j < 4; j++) {
            const int col = t0 + warp_n * 32 + j * 8 + c0;
            if (col >= max_dim) continue;
            float2 v0, v1;
            if (col < T) {   // T even, col even -> col+1 < T too
                const float br0 = g_br[toff + col], br1 = g_br[toff + col + 1];
                v0 = make_float2(acc[i][j][0] + br0, acc[i][j][1] + br1);
                v1 = make_float2(acc[i][j][2] + br0, acc[i][j][3] + br1);
            } else {
                v0 = make_float2(0.f, 0.f);
                v1 = v0;
            }
            *reinterpret_cast<float2*>(outBase + (size_t)rowA * max_dim + col) = v0;
            *reinterpret_cast<float2*>(outBase + (size_t)(rowA + 8) * max_dim + col) = v1;
        }
    }
}

// ----------------------------------------------------------------------------
extern "C" void kernel_launch(void* const* d_in, const int* in_sizes, int n_in,
                              void* d_out, int out_size)
{
    const float* x     = (const float*)d_in[0];
    const int*   psz   = (const int*)d_in[1];
    const float* W_in  = (const float*)d_in[2];
    const float* b_in  = (const float*)d_in[3];
    const float* W_sh  = (const float*)d_in[4];
    const float* b_sh  = (const float*)d_in[5];
    const float* W_res = (const float*)d_in[6];
    const float* b_res = (const float*)d_in[7];
    float* out = (float*)d_out;

    const int max_dim = out_size / (NSAMP * PTOK);

    cudaFuncSetAttribute(gemm1_kernel, cudaFuncAttributeMaxDynamicSharedMemorySize, SMEM_TOTAL);
    cudaFuncSetAttribute(head_kernel,  cudaFuncAttributeMaxDynamicSharedMemorySize, SMEM_TOTAL);

    // 1) split x / W_in into bf16 hi/lo
    {
        const long total = (long)MROWS * EMBED + (long)INTER * EMBED;
        split_inputs_kernel<<<(unsigned)((total + 255) / 256), 256>>>(x, W_in);
    }
    // 2) interpolated head weights (bf16 hi/lo, t-major) + fp32 biases
    {
        const long total = (long)TTOT * INTER + (long)TTOT * EMBED + 2L * TTOT;
        build_weights_kernel<<<(unsigned)((total + 255) / 256), 256>>>(W_sh, b_sh, W_res, b_res);
    }
    // 3) xs = x @ W_in^T + b_in
    {
        dim3 g(INTER / 128, MROWS / 128);   // (32, 256)
        gemm1_kernel<<<g, 256, SMEM_TOTAL>>>(b_in);
    }
    // 4) fused per-sample heads + zero padding
    {
        dim3 g((max_dim + 127) / 128, NSAMP);
        head_kernel<<<g, 256, SMEM_TOTAL>>>(psz, out, max_dim);
    }
}